// round 7
// baseline (speedup 1.0000x reference)
#include <cuda_runtime.h>
#include <float.h>

// Problem constants
#define B_   16
#define P_   4096
#define T_   1024
#define G_   64                 // 64x64 cells of size 8.0 covering [0,512)
#define NC_  (G_*G_)
#define CAP_ 16
#define RADIUS_ 2.5f

#define NB_   148               // exactly 1 block per SM -> perfectly balanced, co-resident
#define NT_   448               // 14 warps; 148*448 = 66304 >= 65536 -> <=1 item per thread
#define NW_   (NT_/32)          // 14

#define SCALE_ 17179869184.0    // 2^34 fixed-point scale (sums < 2^53, exact in int64)

// Scratch (device globals; statically zero-initialized at module load).
// Invariant: every launch leaves all state "empty" for the next replay.
__device__ int                g_cnt [B_*NC_];       // cleared in phase C
__device__ float4             g_cell[B_*NC_*CAP_];  // guarded by g_cnt
__device__ int                g_ovfn[B_];           // cleared in phase C
__device__ float4             g_ovf [B_*T_];        // guarded by g_ovfn
__device__ unsigned long long g_best[B_*T_];   // atomicMax of ~((dsq<<32)|p); 0=empty; cleared in C
__device__ float              g_mind[B_*P_];   // fully overwritten each launch in phase B
__device__ unsigned long long g_claim[B_*P_];  // epoch tags; monotonic, never cleared
__device__ unsigned long long g_acc_obj;       // fixed-point Σ bce_base        (reset by last block)
__device__ unsigned long long g_acc_cobj;      // fixed-point Σ_{correct} conf  (reset by last block)
__device__ unsigned long long g_acc_creg;      // fixed-point Σ_{correct} sigm  (reset by last block)
__device__ unsigned long long g_bar;           // monotonic ticket barrier
__device__ unsigned int       g_done;          // monotonic last-block counter

// Grid barrier; returns the (launch-unique, monotonic) release ticket.
__device__ __forceinline__ unsigned long long gbar() {
    __shared__ unsigned long long sh_tgt;
    __syncthreads();
    if (threadIdx.x == 0) {
        __threadfence();
        unsigned long long my  = atomicAdd(&g_bar, 1ull);
        unsigned long long tgt = (my / NB_ + 1ull) * NB_;
        while (*((volatile unsigned long long*)&g_bar) < tgt) __nanosleep(32);
        sh_tgt = tgt;
    }
    __syncthreads();
    return sh_tgt;
}

__device__ __forceinline__ long long wred(long long v) {
    #pragma unroll
    for (int o = 16; o; o >>= 1) v += __shfl_down_sync(0xFFFFFFFFu, v, o);
    return v;
}

__device__ __forceinline__ void consider(float4 v, float cls, float x, float y,
                                         int p, unsigned long long* bestBase,
                                         float& mind) {
    float dx = x - v.y, dy = y - v.z;
    float dsq = dx*dx + dy*dy;
    mind = fminf(mind, dsq);
    float d = sqrtf(dsq + 1e-12f);
    if (d <= RADIUS_ && cls == v.x) {
        int t = __float_as_int(v.w);
        // min over (dsq, p) lexicographic == max over bitwise-NOT; 0 stays "empty"
        unsigned long long key = ~(((unsigned long long)__float_as_uint(dsq) << 32)
                                   | (unsigned int)p);
        atomicMax(bestBase + t, key);
    }
}

__global__ void __launch_bounds__(NT_, 1)
fused_kernel(const float* __restrict__ pred, const float* __restrict__ gt,
             float* __restrict__ out) {
    const int tid  = threadIdx.x;
    const int i0   = blockIdx.x * NT_ + tid;   // < 66304; guard vs 65536
    const int lane = tid & 31;
    const int wid  = tid >> 5;
    const bool has = (i0 < B_*P_);
    const float4* __restrict__ pred4 = reinterpret_cast<const float4*>(pred);

    // ---- Phase A: bin targets + compute base bce (accumulate LOCALLY) ----
    long long accO = 0;
    float4 myPred = make_float4(0.f, 0.f, 0.f, 0.f);
    if (has) {
        myPred = __ldg(pred4 + i0);                   // {cls,x,y,conf} — reused in phase B
        float c = myPred.w;
        float bce0 = fmaxf(c, 0.0f) + log1pf(expf(-fabsf(c)));  // BCE with target 0
        accO = (long long)((double)bce0 * SCALE_);    // deferred to final RED
    }
    if (i0 < B_*T_) {                                 // bin target i0
        int b = i0 >> 10;
        int t = i0 & (T_ - 1);
        const float* g = gt + (size_t)i0 * 3;
        float tc = g[0], tx = g[1], ty = g[2];
        int cx = (int)(tx * 0.125f); cx = min(max(cx, 0), G_-1);
        int cy = (int)(ty * 0.125f); cy = min(max(cy, 0), G_-1);
        int cidx = b*NC_ + cy*G_ + cx;
        int pos = atomicAdd(&g_cnt[cidx], 1);
        float4 v = make_float4(tc, tx, ty, __int_as_float(t));
        if (pos < CAP_) {
            g_cell[cidx*CAP_ + pos] = v;
        } else {
            int j = atomicAdd(&g_ovfn[b], 1);
            g_ovf[b*T_ + j] = v;
        }
    }

    gbar();

    // ---- Phase B: per-pred 2x2 neighborhood scan (radius 2.5 < cell/2=4) -
    if (has) {
        int b = i0 >> 12;
        int p = i0 & (P_ - 1);
        float cls = myPred.x, x = myPred.y, y = myPred.z;

        int cx = (int)(x * 0.125f); cx = min(max(cx, 0), G_-1);
        int cy = (int)(y * 0.125f); cy = min(max(cy, 0), G_-1);
        float fx = x - (float)cx * 8.0f;
        float fy = y - (float)cy * 8.0f;
        int nx = cx + ((fx <= RADIUS_) ? -1 : ((fx >= 8.0f - RADIUS_) ? 1 : 0));
        int ny = cy + ((fy <= RADIUS_) ? -1 : ((fy >= 8.0f - RADIUS_) ? 1 : 0));
        bool vx = (nx != cx) & (nx >= 0) & (nx < G_);
        bool vy = (ny != cy) & (ny >= 0) & (ny < G_);

        int  cell[4];
        bool ok[4];
        cell[0] = b*NC_ + cy*G_ + cx;                 ok[0] = true;
        cell[1] = vx ? (b*NC_ + cy*G_ + nx) : b*NC_;  ok[1] = vx;
        cell[2] = vy ? (b*NC_ + ny*G_ + cx) : b*NC_;  ok[2] = vy;
        cell[3] = (vx & vy) ? (b*NC_ + ny*G_ + nx) : b*NC_;  ok[3] = vx & vy;

        // Front-batch: 4 counts + 4 speculative slot-0 loads, all independent.
        int    ccnt[4];
        float4 s0[4];
        #pragma unroll
        for (int k = 0; k < 4; k++) {
            ccnt[k] = ok[k] ? __ldcg(&g_cnt[cell[k]]) : 0;
            s0[k]   = __ldcg(&g_cell[cell[k]*CAP_]);  // masked by ccnt below
        }

        unsigned long long* bestBase = g_best + b*T_;
        float mind = FLT_MAX;
        #pragma unroll
        for (int k = 0; k < 4; k++) {
            int cnt = min(ccnt[k], CAP_);
            if (cnt > 0) consider(s0[k], cls, x, y, p, bestBase, mind);
            const float4* slot = &g_cell[cell[k]*CAP_];
            for (int j = 1; j < cnt; j++)             // rare (~2.6%)
                consider(__ldcg(slot + j), cls, x, y, p, bestBase, mind);
        }
        int novf = __ldcg(&g_ovfn[b]);                // normally 0
        for (int j = 0; j < novf; j++)
            consider(__ldcg(&g_ovf[b*T_ + j]), cls, x, y, p, bestBase, mind);

        g_mind[i0] = mind;
    }

    unsigned long long epoch = gbar();                // launch-unique, > 0

    // ---- Phase C: exactly-once corrections + cleanup ---------------------
    long long accCO = 0, accCR = 0;
    if (has)     g_cnt[i0]  = 0;                      // B_*NC_ == B_*P_
    if (i0 < B_) g_ovfn[i0] = 0;
    if (i0 < B_*T_) {
        unsigned long long v = __ldcg(&g_best[i0]);
        g_best[i0] = 0;                               // reset for next launch
        if (v) {
            unsigned long long vi = ~v;
            int p  = (int)(vi & 0xFFFFFFFFull);
            int b  = i0 >> 10;
            int pi = b*P_ + p;
            // Issue data loads before (independent of) the claim atomic.
            float conf = __ldg(&pred[4*pi + 3]);
            float dmin = __ldcg(&g_mind[pi]);
            if (atomicExch(&g_claim[pi], epoch) != epoch) {   // exactly-once owner
                float d = sqrtf(dmin + 1e-12f);
                float s = 1.0f / (1.0f + expf(-(RADIUS_ - d)));
                accCO = (long long)((double)conf * SCALE_);
                accCR = (long long)((double)s    * SCALE_);
            }
        }
    }

    // ---- Final: per-block smem reduction, then 3 REDs per block ----------
    __shared__ long long s_o[NW_], s_co[NW_], s_cr[NW_];
    accO  = wred(accO);
    accCO = wred(accCO);
    accCR = wred(accCR);
    if (lane == 0) { s_o[wid] = accO; s_co[wid] = accCO; s_cr[wid] = accCR; }
    __syncthreads();
    if (tid == 0) {
        long long to = 0, tco = 0, tcr = 0;
        #pragma unroll
        for (int w = 0; w < NW_; w++) { to += s_o[w]; tco += s_co[w]; tcr += s_cr[w]; }
        if (to)  atomicAdd(&g_acc_obj,  (unsigned long long)to);
        if (tco) atomicAdd(&g_acc_cobj, (unsigned long long)tco);
        if (tcr) atomicAdd(&g_acc_creg, (unsigned long long)tcr);
        __threadfence();
        unsigned int t = atomicAdd(&g_done, 1u);
        if ((t % NB_) == (NB_ - 1u)) {                // last block finalizes
            long long o  = (long long)atomicAdd(&g_acc_obj,  0ull);
            long long co = (long long)atomicAdd(&g_acc_cobj, 0ull);
            long long cr = (long long)atomicAdd(&g_acc_creg, 0ull);
            double inv = 1.0 / (SCALE_ * 65536.0);
            out[0] = (float)(((double)o - (double)co) * inv);   // obj_loss
            out[1] = (float)(1.0 - (double)cr * inv);           // reg_loss
            atomicExch(&g_acc_obj,  0ull);                      // reset for next replay
            atomicExch(&g_acc_cobj, 0ull);
            atomicExch(&g_acc_creg, 0ull);
        }
    }
}

extern "C" void kernel_launch(void* const* d_in, const int* in_sizes, int n_in,
                              void* d_out, int out_size) {
    const float* pred = (const float*)d_in[0];
    const float* gt   = (const float*)d_in[1];
    if (n_in >= 2 && in_sizes[0] == B_*T_*3) {   // defensive input-order check
        const float* tmp = pred; pred = gt; gt = tmp;
    }
    (void)out_size;
    fused_kernel<<<NB_, NT_>>>(pred, gt, (float*)d_out);
}